// round 2
// baseline (speedup 1.0000x reference)
#include <cuda_runtime.h>

// Problem constants
#define BB 4
#define SS 2048
#define DD 1024
#define HH 16
#define DKK 64
#define MM (BB * SS)   // 8192 rows

// Scratch (device globals: allocation-free per harness rules)
__device__ float g_q[MM * DD];
__device__ float g_k[MM * DD];
__device__ float g_v[MM * DD];
__device__ float g_attn[MM * DD];

// ---------------------------------------------------------------------------
// 128x128x8 fp32 SGEMM tile, C = A * B^T  (A: MxK row-major, B: NxK row-major)
// 256 threads, 8x8 accumulators per thread.
// ---------------------------------------------------------------------------
__device__ __forceinline__ void gemm128_nt(const float* __restrict__ A,
                                           const float* __restrict__ Bm,
                                           float* __restrict__ C,
                                           int N, int K) {
    __shared__ __align__(16) float As[8][132];
    __shared__ __align__(16) float Bs[8][132];
    const int m0 = blockIdx.y * 128;
    const int n0 = blockIdx.x * 128;
    const int tid = threadIdx.x;
    const int tx = tid & 15;        // 0..15 -> N direction
    const int ty = tid >> 4;        // 0..15 -> M direction
    const int lrow = tid >> 1;      // 0..127 load row
    const int lk = (tid & 1) << 2;  // 0 or 4

    float acc[8][8];
#pragma unroll
    for (int i = 0; i < 8; i++)
#pragma unroll
        for (int j = 0; j < 8; j++) acc[i][j] = 0.f;

    const float* Ap = A + (m0 + lrow) * K + lk;
    const float* Bp = Bm + (n0 + lrow) * K + lk;

    for (int kt = 0; kt < K; kt += 8) {
        float4 av = *(const float4*)(Ap + kt);
        float4 bv = *(const float4*)(Bp + kt);
        __syncthreads();
        As[lk + 0][lrow] = av.x;
        As[lk + 1][lrow] = av.y;
        As[lk + 2][lrow] = av.z;
        As[lk + 3][lrow] = av.w;
        Bs[lk + 0][lrow] = bv.x;
        Bs[lk + 1][lrow] = bv.y;
        Bs[lk + 2][lrow] = bv.z;
        Bs[lk + 3][lrow] = bv.w;
        __syncthreads();
#pragma unroll
        for (int k = 0; k < 8; k++) {
            float a[8], b[8];
            *(float4*)&a[0] = *(const float4*)&As[k][ty * 8];
            *(float4*)&a[4] = *(const float4*)&As[k][ty * 8 + 4];
            *(float4*)&b[0] = *(const float4*)&Bs[k][tx * 8];
            *(float4*)&b[4] = *(const float4*)&Bs[k][tx * 8 + 4];
#pragma unroll
            for (int i = 0; i < 8; i++)
#pragma unroll
                for (int j = 0; j < 8; j++)
                    acc[i][j] = fmaf(a[i], b[j], acc[i][j]);
        }
    }

#pragma unroll
    for (int i = 0; i < 8; i++) {
        float* Cp = C + (m0 + ty * 8 + i) * N + (n0 + tx * 8);
        *(float4*)(Cp) = make_float4(acc[i][0], acc[i][1], acc[i][2], acc[i][3]);
        *(float4*)(Cp + 4) = make_float4(acc[i][4], acc[i][5], acc[i][6], acc[i][7]);
    }
}

// Q/K/V projections: gridDim.z selects weight & destination.
__global__ void __launch_bounds__(256) qkv_proj_kernel(
    const float* __restrict__ x, const float* __restrict__ wq,
    const float* __restrict__ wk, const float* __restrict__ wv) {
    const float* w;
    float* out;
    if (blockIdx.z == 0) { w = wq; out = g_q; }
    else if (blockIdx.z == 1) { w = wk; out = g_k; }
    else { w = wv; out = g_v; }
    gemm128_nt(x, w, out, DD, DD);
}

// Output projection: out = attn * wo^T
__global__ void __launch_bounds__(256) out_proj_kernel(
    const float* __restrict__ wo, float* __restrict__ out) {
    gemm128_nt(g_attn, wo, out, DD, DD);
}

// ---------------------------------------------------------------------------
// Causal flash attention, fp32. 128 queries per CTA (1 row per thread),
// 32-key K/V tiles in smem, online softmax.
// ---------------------------------------------------------------------------
__global__ void __launch_bounds__(128) attn_kernel() {
    __shared__ __align__(16) float Ks[32][64];
    __shared__ __align__(16) float Vs[32][64];

    const int r = threadIdx.x;          // 0..127
    const int qt = blockIdx.x;          // 0..15  (query tile)
    const int bh = blockIdx.y;          // 0..63
    const int b = bh >> 4;
    const int h = bh & 15;
    const int qs = qt * 128;
    const int qi = qs + r;              // this thread's query index

    const float* qrow = g_q + (b * SS + qi) * DD + h * DKK;
    float q[64];
#pragma unroll
    for (int i = 0; i < 16; i++) {
        float4 t = *(const float4*)(qrow + i * 4);
        q[i * 4 + 0] = t.x * 0.125f;   // 1/sqrt(64) folded into q
        q[i * 4 + 1] = t.y * 0.125f;
        q[i * 4 + 2] = t.z * 0.125f;
        q[i * 4 + 3] = t.w * 0.125f;
    }

    float m = -1e30f, l = 0.f;
    float acc[64];
#pragma unroll
    for (int d = 0; d < 64; d++) acc[d] = 0.f;

    const float* kbase = g_k + (b * SS) * DD + h * DKK;
    const float* vbase = g_v + (b * SS) * DD + h * DKK;

    const int ktiles = (qs + 128) / 32;   // keys needed: 0 .. qs+127
    for (int kt = 0; kt < ktiles; kt++) {
        const int ks0 = kt * 32;
        __syncthreads();
#pragma unroll
        for (int i = 0; i < 4; i++) {
            int f = r + i * 128;          // 0..511 float4 slots
            int row = f >> 4;
            int c = (f & 15) * 4;
            *(float4*)&Ks[row][c] = *(const float4*)(kbase + (ks0 + row) * DD + c);
            *(float4*)&Vs[row][c] = *(const float4*)(vbase + (ks0 + row) * DD + c);
        }
        __syncthreads();

        float s[32];
#pragma unroll
        for (int j = 0; j < 32; j++) {
            float sv = 0.f;
#pragma unroll
            for (int d4 = 0; d4 < 16; d4++) {
                float4 kv = *(const float4*)&Ks[j][d4 * 4];
                sv = fmaf(q[d4 * 4 + 0], kv.x, sv);
                sv = fmaf(q[d4 * 4 + 1], kv.y, sv);
                sv = fmaf(q[d4 * 4 + 2], kv.z, sv);
                sv = fmaf(q[d4 * 4 + 3], kv.w, sv);
            }
            s[j] = (ks0 + j <= qi) ? sv : -1e30f;
        }

        float mt = -1e30f;
#pragma unroll
        for (int j = 0; j < 32; j++) mt = fmaxf(mt, s[j]);
        float mn = fmaxf(m, mt);
        float corr = __expf(m - mn);
        l *= corr;
#pragma unroll
        for (int d = 0; d < 64; d++) acc[d] *= corr;

        float ps = 0.f;
#pragma unroll
        for (int j = 0; j < 32; j++) {
            float p = __expf(s[j] - mn);
            ps += p;
            s[j] = p;
        }
        l += ps;
        m = mn;

#pragma unroll
        for (int j = 0; j < 32; j++) {
            float p = s[j];
#pragma unroll
            for (int d4 = 0; d4 < 16; d4++) {
                float4 vv = *(const float4*)&Vs[j][d4 * 4];
                acc[d4 * 4 + 0] = fmaf(p, vv.x, acc[d4 * 4 + 0]);
                acc[d4 * 4 + 1] = fmaf(p, vv.y, acc[d4 * 4 + 1]);
                acc[d4 * 4 + 2] = fmaf(p, vv.z, acc[d4 * 4 + 2]);
                acc[d4 * 4 + 3] = fmaf(p, vv.w, acc[d4 * 4 + 3]);
            }
        }
    }

    const float inv = 1.f / l;
    float* orow = g_attn + (b * SS + qi) * DD + h * DKK;
#pragma unroll
    for (int i = 0; i < 16; i++) {
        float4 t;
        t.x = acc[i * 4 + 0] * inv;
        t.y = acc[i * 4 + 1] * inv;
        t.z = acc[i * 4 + 2] * inv;
        t.w = acc[i * 4 + 3] * inv;
        *(float4*)(orow + i * 4) = t;
    }
}

// ---------------------------------------------------------------------------
extern "C" void kernel_launch(void* const* d_in, const int* in_sizes, int n_in,
                              void* d_out, int out_size) {
    const float* x  = (const float*)d_in[0];
    const float* wq = (const float*)d_in[1];
    const float* wk = (const float*)d_in[2];
    const float* wv = (const float*)d_in[3];
    const float* wo = (const float*)d_in[4];
    float* out = (float*)d_out;

    // Q/K/V projections: 3 x (8192x1024) * (1024x1024)^T
    dim3 gproj(DD / 128, MM / 128, 3);
    qkv_proj_kernel<<<gproj, 256>>>(x, wq, wk, wv);

    // Causal flash attention
    dim3 gattn(SS / 128, BB * HH);
    attn_kernel<<<gattn, 128>>>();

    // Output projection
    dim3 gout(DD / 128, MM / 128, 1);
    out_proj_kernel<<<gout, 256>>>(wo, out);
}

// round 7
// speedup vs baseline: 1.4919x; 1.4919x over previous
#include <cuda_runtime.h>
#include <cstdint>

// Problem constants
#define BB 4
#define SS 2048
#define DD 1024
#define HH 16
#define DKK 64
#define MM (BB * SS)   // 8192 rows

// Scratch (device globals: allocation-free per harness rules)
__device__ float g_x [MM * DD];   // x rounded to tf32
__device__ float g_wq[DD * DD];
__device__ float g_wk[DD * DD];
__device__ float g_wv[DD * DD];
__device__ float g_wo[DD * DD];
__device__ float g_q [MM * DD];
__device__ float g_k [MM * DD];
__device__ float g_v [MM * DD];
__device__ float g_attn[MM * DD];

// ---------------------------------------------------------------------------
// Helpers
// ---------------------------------------------------------------------------
__device__ __forceinline__ uint32_t smem_u32(const void* p) {
    uint32_t a;
    asm("{ .reg .u64 t; cvta.to.shared.u64 t, %1; cvt.u32.u64 %0, t; }" : "=r"(a) : "l"(p));
    return a;
}

__device__ __forceinline__ void cp16(uint32_t saddr, const float* g) {
    asm volatile("cp.async.cg.shared.global [%0], [%1], 16;" :: "r"(saddr), "l"(g));
}

// m16n8k8 tf32 MMA (sm_80+, works on base compute_103 target)
__device__ __forceinline__ void mma_tf32(float* d, const uint32_t* a, const uint32_t* b) {
    asm volatile(
        "mma.sync.aligned.m16n8k8.row.col.f32.tf32.tf32.f32 "
        "{%0,%1,%2,%3}, {%4,%5,%6,%7}, {%8,%9}, {%0,%1,%2,%3};"
        : "+f"(d[0]), "+f"(d[1]), "+f"(d[2]), "+f"(d[3])
        : "r"(a[0]), "r"(a[1]), "r"(a[2]), "r"(a[3]), "r"(b[0]), "r"(b[1]));
}

// ---------------------------------------------------------------------------
// tf32 tensor-core GEMM: C = A(MxK, K-major) * B(NxK, K-major)^T
// CTA tile 128x128, 256 threads (8 warps, 4x2), warp tile 32x64.
// cp.async double-buffered BK=32 chunks, padded smem (conflict-free frags).
// ---------------------------------------------------------------------------
#define BK 32
#define LDS_ROW 36                         // 32 + 4 pad floats (16B aligned rows)
#define STAGE_FLOATS (128 * LDS_ROW)       // 4608 floats per operand stage
#define SMEM_BYTES_G (4 * STAGE_FLOATS * 4)  // 2 ops x 2 stages = 73728 B

__device__ __forceinline__ void gemm_body(const float* __restrict__ A,
                                          const float* __restrict__ B,
                                          float* __restrict__ C) {
    extern __shared__ float smem[];
    float* As = smem;                         // [2][128][36]
    float* Ws = smem + 2 * STAGE_FLOATS;      // [2][128][36]
    const uint32_t sA = smem_u32(As);
    const uint32_t sW = smem_u32(Ws);

    const int tid = threadIdx.x;
    const int w = tid >> 5, lane = tid & 31;
    const int g = lane >> 2, q = lane & 3;
    const int wm = (w & 3) * 32;              // warp M offset in tile
    const int wn = (w >> 2) * 64;             // warp N offset in tile
    const int m0 = blockIdx.y * 128;
    const int n0 = blockIdx.x * 128;

    const float* Ag = A + (size_t)m0 * DD;
    const float* Wg = B + (size_t)n0 * DD;

    float acc[2][8][4];
#pragma unroll
    for (int mt = 0; mt < 2; mt++)
#pragma unroll
        for (int nt = 0; nt < 8; nt++)
#pragma unroll
            for (int i = 0; i < 4; i++) acc[mt][nt][i] = 0.f;

    // issue cp.async for chunk -> stage
#define ISSUE(chunk, st) do {                                                  \
        int _c = (chunk), _s = (st);                                           \
        _Pragma("unroll")                                                      \
        for (int i = 0; i < 4; i++) {                                          \
            int f = i * 256 + tid;           /* 0..1023 float4 slots */        \
            int row = f >> 3, seg = f & 7;                                     \
            uint32_t off = (uint32_t)((_s * STAGE_FLOATS + row * LDS_ROW + seg * 4) * 4); \
            cp16(sA + off, Ag + (size_t)row * DD + _c * BK + seg * 4);         \
            cp16(sW + off, Wg + (size_t)row * DD + _c * BK + seg * 4);         \
        }                                                                      \
        asm volatile("cp.async.commit_group;" ::: "memory");                   \
    } while (0)

    ISSUE(0, 0);
    const int NCH = DD / BK;  // 32
    for (int c = 0; c < NCH; c++) {
        const int st = c & 1;
        if (c + 1 < NCH) {
            ISSUE(c + 1, st ^ 1);
            asm volatile("cp.async.wait_group 1;" ::: "memory");
        } else {
            asm volatile("cp.async.wait_group 0;" ::: "memory");
        }
        __syncthreads();

        const float* as = As + st * STAGE_FLOATS;
        const float* ws = Ws + st * STAGE_FLOATS;
#pragma unroll
        for (int kk = 0; kk < 4; kk++) {
            const int k0 = kk * 8;
            uint32_t af[2][4], bf[8][2];
#pragma unroll
            for (int mt = 0; mt < 2; mt++) {
                const float* base = as + (wm + mt * 16 + g) * LDS_ROW + k0;
                af[mt][0] = __float_as_uint(base[q]);
                af[mt][1] = __float_as_uint(base[8 * LDS_ROW + q]);
                af[mt][2] = __float_as_uint(base[q + 4]);
                af[mt][3] = __float_as_uint(base[8 * LDS_ROW + q + 4]);
            }
#pragma unroll
            for (int nt = 0; nt < 8; nt++) {
                const float* base = ws + (wn + nt * 8 + g) * LDS_ROW + k0;
                bf[nt][0] = __float_as_uint(base[q]);
                bf[nt][1] = __float_as_uint(base[q + 4]);
            }
#pragma unroll
            for (int mt = 0; mt < 2; mt++)
#pragma unroll
                for (int nt = 0; nt < 8; nt++)
                    mma_tf32(acc[mt][nt], af[mt], bf[nt]);
        }
        __syncthreads();
    }
#undef ISSUE

    // Epilogue: c0->(g,2q) c1->(g,2q+1) c2->(g+8,2q) c3->(g+8,2q+1)
#pragma unroll
    for (int mt = 0; mt < 2; mt++) {
#pragma unroll
        for (int nt = 0; nt < 8; nt++) {
            const int r0 = m0 + wm + mt * 16 + g;
            const int cc = n0 + wn + nt * 8 + 2 * q;
            float2 v0 = make_float2(acc[mt][nt][0], acc[mt][nt][1]);
            float2 v1 = make_float2(acc[mt][nt][2], acc[mt][nt][3]);
            *(float2*)(C + (size_t)r0 * DD + cc) = v0;
            *(float2*)(C + (size_t)(r0 + 8) * DD + cc) = v1;
        }
    }
}

__global__ void __launch_bounds__(256) gemm_qkv_kernel() {
    const float* B;
    float* C;
    if (blockIdx.z == 0) { B = g_wq; C = g_q; }
    else if (blockIdx.z == 1) { B = g_wk; C = g_k; }
    else { B = g_wv; C = g_v; }
    gemm_body(g_x, B, C);
}

__global__ void __launch_bounds__(256) gemm_out_kernel(float* __restrict__ out) {
    gemm_body(g_attn, g_wo, out);
}

// ---------------------------------------------------------------------------
// Round fp32 -> nearest tf32 (unbiased tensor-core inputs)
// ---------------------------------------------------------------------------
__global__ void __launch_bounds__(256) round_tf32_kernel(const float* __restrict__ in,
                                                         float* __restrict__ out, int n4) {
    int i = blockIdx.x * blockDim.x + threadIdx.x;
    if (i < n4) {
        float4 v = ((const float4*)in)[i];
        uint32_t a, b, c, d;
        asm("cvt.rna.tf32.f32 %0, %1;" : "=r"(a) : "f"(v.x));
        asm("cvt.rna.tf32.f32 %0, %1;" : "=r"(b) : "f"(v.y));
        asm("cvt.rna.tf32.f32 %0, %1;" : "=r"(c) : "f"(v.z));
        asm("cvt.rna.tf32.f32 %0, %1;" : "=r"(d) : "f"(v.w));
        float4 o;
        o.x = __uint_as_float(a);
        o.y = __uint_as_float(b);
        o.z = __uint_as_float(c);
        o.w = __uint_as_float(d);
        ((float4*)out)[i] = o;
    }
}

// ---------------------------------------------------------------------------
// Causal flash attention, fp32 (validated in R2). Output rounded to tf32-rna
// so the W_O tensor-core GEMM sees unbiased operands.
// ---------------------------------------------------------------------------
__global__ void __launch_bounds__(128) attn_kernel() {
    __shared__ __align__(16) float Ks[32][64];
    __shared__ __align__(16) float Vs[32][64];

    const int r = threadIdx.x;
    const int qt = blockIdx.x;
    const int bh = blockIdx.y;
    const int b = bh >> 4;
    const int h = bh & 15;
    const int qs = qt * 128;
    const int qi = qs + r;

    const float* qrow = g_q + (size_t)(b * SS + qi) * DD + h * DKK;
    float q[64];
#pragma unroll
    for (int i = 0; i < 16; i++) {
        float4 t = *(const float4*)(qrow + i * 4);
        q[i * 4 + 0] = t.x * 0.125f;
        q[i * 4 + 1] = t.y * 0.125f;
        q[i * 4 + 2] = t.z * 0.125f;
        q[i * 4 + 3] = t.w * 0.125f;
    }

    float m = -1e30f, l = 0.f;
    float acc[64];
#pragma unroll
    for (int d = 0; d < 64; d++) acc[d] = 0.f;

    const float* kbase = g_k + (size_t)(b * SS) * DD + h * DKK;
    const float* vbase = g_v + (size_t)(b * SS) * DD + h * DKK;

    const int ktiles = (qs + 128) / 32;
    for (int kt = 0; kt < ktiles; kt++) {
        const int ks0 = kt * 32;
        __syncthreads();
#pragma unroll
        for (int i = 0; i < 4; i++) {
            int f = r + i * 128;
            int rowk = f >> 4;
            int c = (f & 15) * 4;
            *(float4*)&Ks[rowk][c] = *(const float4*)(kbase + (size_t)(ks0 + rowk) * DD + c);
            *(float4*)&Vs[rowk][c] = *(const float4*)(vbase + (size_t)(ks0 + rowk) * DD + c);
        }
        __syncthreads();

        float s[32];
#pragma unroll
        for (int j = 0; j < 32; j++) {
            float sv = 0.f;
#pragma unroll
            for (int d4 = 0; d4 < 16; d4++) {
                float4 kv = *(const float4*)&Ks[j][d4 * 4];
                sv = fmaf(q[d4 * 4 + 0], kv.x, sv);
                sv = fmaf(q[d4 * 4 + 1], kv.y, sv);
                sv = fmaf(q[d4 * 4 + 2], kv.z, sv);
                sv = fmaf(q[d4 * 4 + 3], kv.w, sv);
            }
            s[j] = (ks0 + j <= qi) ? sv : -1e30f;
        }

        float mt = -1e30f;
#pragma unroll
        for (int j = 0; j < 32; j++) mt = fmaxf(mt, s[j]);
        float mn = fmaxf(m, mt);
        float corr = __expf(m - mn);
        l *= corr;
#pragma unroll
        for (int d = 0; d < 64; d++) acc[d] *= corr;

        float ps = 0.f;
#pragma unroll
        for (int j = 0; j < 32; j++) {
            float p = __expf(s[j] - mn);
            ps += p;
            s[j] = p;
        }
        l += ps;
        m = mn;

#pragma unroll
        for (int j = 0; j < 32; j++) {
            float p = s[j];
#pragma unroll
            for (int d4 = 0; d4 < 16; d4++) {
                float4 vv = *(const float4*)&Vs[j][d4 * 4];
                acc[d4 * 4 + 0] = fmaf(p, vv.x, acc[d4 * 4 + 0]);
                acc[d4 * 4 + 1] = fmaf(p, vv.y, acc[d4 * 4 + 1]);
                acc[d4 * 4 + 2] = fmaf(p, vv.z, acc[d4 * 4 + 2]);
                acc[d4 * 4 + 3] = fmaf(p, vv.w, acc[d4 * 4 + 3]);
            }
        }
    }

    const float inv = 1.f / l;
    float* orow = g_attn + (size_t)(b * SS + qi) * DD + h * DKK;
#pragma unroll
    for (int i = 0; i < 16; i++) {
        uint32_t u0, u1, u2, u3;
        asm("cvt.rna.tf32.f32 %0, %1;" : "=r"(u0) : "f"(acc[i * 4 + 0] * inv));
        asm("cvt.rna.tf32.f32 %0, %1;" : "=r"(u1) : "f"(acc[i * 4 + 1] * inv));
        asm("cvt.rna.tf32.f32 %0, %1;" : "=r"(u2) : "f"(acc[i * 4 + 2] * inv));
        asm("cvt.rna.tf32.f32 %0, %1;" : "=r"(u3) : "f"(acc[i * 4 + 3] * inv));
        float4 t;
        t.x = __uint_as_float(u0);
        t.y = __uint_as_float(u1);
        t.z = __uint_as_float(u2);
        t.w = __uint_as_float(u3);
        *(float4*)(orow + i * 4) = t;
    }
}

// ---------------------------------------------------------------------------
extern "C" void kernel_launch(void* const* d_in, const int* in_sizes, int n_in,
                              void* d_out, int out_size) {
    const float* x  = (const float*)d_in[0];
    const float* wq = (const float*)d_in[1];
    const float* wk = (const float*)d_in[2];
    const float* wv = (const float*)d_in[3];
    const float* wo = (const float*)d_in[4];
    float* out = (float*)d_out;

    cudaFuncSetAttribute(gemm_qkv_kernel, cudaFuncAttributeMaxDynamicSharedMemorySize, SMEM_BYTES_G);
    cudaFuncSetAttribute(gemm_out_kernel, cudaFuncAttributeMaxDynamicSharedMemorySize, SMEM_BYTES_G);

    float *px, *pwq, *pwk, *pwv, *pwo;
    cudaGetSymbolAddress((void**)&px,  g_x);
    cudaGetSymbolAddress((void**)&pwq, g_wq);
    cudaGetSymbolAddress((void**)&pwk, g_wk);
    cudaGetSymbolAddress((void**)&pwv, g_wv);
    cudaGetSymbolAddress((void**)&pwo, g_wo);

    // Round all GEMM operands to nearest-tf32
    const int nx4 = MM * DD / 4, nw4 = DD * DD / 4;
    round_tf32_kernel<<<(nx4 + 255) / 256, 256>>>(x, px, nx4);
    round_tf32_kernel<<<(nw4 + 255) / 256, 256>>>(wq, pwq, nw4);
    round_tf32_kernel<<<(nw4 + 255) / 256, 256>>>(wk, pwk, nw4);
    round_tf32_kernel<<<(nw4 + 255) / 256, 256>>>(wv, pwv, nw4);
    round_tf32_kernel<<<(nw4 + 255) / 256, 256>>>(wo, pwo, nw4);

    // Q/K/V projections on tensor cores (tf32 mma.sync)
    dim3 gproj(DD / 128, MM / 128, 3);
    gemm_qkv_kernel<<<gproj, 256, SMEM_BYTES_G>>>();

    // Causal flash attention (fp32)
    dim3 gattn(SS / 128, BB * HH);
    attn_kernel<<<gattn, 128>>>();

    // Output projection on tensor cores (tf32 mma.sync)
    dim3 gout(DD / 128, MM / 128, 1);
    gemm_out_kernel<<<gout, 256, SMEM_BYTES_G>>>(out);
}

// round 16
// speedup vs baseline: 4.1089x; 2.7542x over previous
#include <cuda_runtime.h>
#include <cstdint>

// Problem constants
#define BB 4
#define SS 2048
#define DD 1024
#define HH 16
#define DKK 64
#define MM (BB * SS)   // 8192 rows

// Scratch (device globals: allocation-free per harness rules)
__device__ float g_x [MM * DD];   // x rounded to tf32
__device__ float g_wq[DD * DD];
__device__ float g_wk[DD * DD];
__device__ float g_wv[DD * DD];
__device__ float g_wo[DD * DD];
__device__ float g_q [MM * DD];   // tf32-rounded (gemm epilogue)
__device__ float g_k [MM * DD];   // tf32-rounded
__device__ float g_v [MM * DD];   // tf32-rounded
__device__ float g_attn[MM * DD]; // tf32-rounded (attn epilogue)

// ---------------------------------------------------------------------------
// Helpers
// ---------------------------------------------------------------------------
__device__ __forceinline__ uint32_t smem_u32(const void* p) {
    uint32_t a;
    asm("{ .reg .u64 t; cvta.to.shared.u64 t, %1; cvt.u32.u64 %0, t; }" : "=r"(a) : "l"(p));
    return a;
}

__device__ __forceinline__ void cp16(uint32_t saddr, const float* g) {
    asm volatile("cp.async.cg.shared.global [%0], [%1], 16;" :: "r"(saddr), "l"(g));
}

__device__ __forceinline__ float rna_tf32(float x) {
    uint32_t u;
    asm("cvt.rna.tf32.f32 %0, %1;" : "=r"(u) : "f"(x));
    return __uint_as_float(u);
}

// m16n8k8 tf32 MMA (sm_80+, compiles on base compute_103 target)
__device__ __forceinline__ void mma_tf32(float* d, const uint32_t* a, const uint32_t* b) {
    asm volatile(
        "mma.sync.aligned.m16n8k8.row.col.f32.tf32.tf32.f32 "
        "{%0,%1,%2,%3}, {%4,%5,%6,%7}, {%8,%9}, {%0,%1,%2,%3};"
        : "+f"(d[0]), "+f"(d[1]), "+f"(d[2]), "+f"(d[3])
        : "r"(a[0]), "r"(a[1]), "r"(a[2]), "r"(a[3]), "r"(b[0]), "r"(b[1]));
}

// ---------------------------------------------------------------------------
// tf32 tensor-core GEMM: C = A(MxK, K-major) * B(NxK, K-major)^T
// CTA tile 128x128, 256 threads (8 warps, 4x2), warp tile 32x64.
// cp.async double-buffered BK=32 chunks. ROUND: emit tf32-rna outputs.
// ---------------------------------------------------------------------------
#define BK 32
#define LDS_ROW 36
#define STAGE_FLOATS (128 * LDS_ROW)
#define SMEM_BYTES_G (4 * STAGE_FLOATS * 4)  // 73728 B

template <bool ROUND>
__device__ __forceinline__ void gemm_body(const float* __restrict__ A,
                                          const float* __restrict__ B,
                                          float* __restrict__ C) {
    extern __shared__ float smem[];
    float* As = smem;
    float* Ws = smem + 2 * STAGE_FLOATS;
    const uint32_t sA = smem_u32(As);
    const uint32_t sW = smem_u32(Ws);

    const int tid = threadIdx.x;
    const int w = tid >> 5, lane = tid & 31;
    const int g = lane >> 2, q = lane & 3;
    const int wm = (w & 3) * 32;
    const int wn = (w >> 2) * 64;
    const int m0 = blockIdx.y * 128;
    const int n0 = blockIdx.x * 128;

    const float* Ag = A + (size_t)m0 * DD;
    const float* Wg = B + (size_t)n0 * DD;

    float acc[2][8][4];
#pragma unroll
    for (int mt = 0; mt < 2; mt++)
#pragma unroll
        for (int nt = 0; nt < 8; nt++)
#pragma unroll
            for (int i = 0; i < 4; i++) acc[mt][nt][i] = 0.f;

#define ISSUE(chunk, st) do {                                                  \
        int _c = (chunk), _s = (st);                                           \
        _Pragma("unroll")                                                      \
        for (int i = 0; i < 4; i++) {                                          \
            int f = i * 256 + tid;                                             \
            int row = f >> 3, seg = f & 7;                                     \
            uint32_t off = (uint32_t)((_s * STAGE_FLOATS + row * LDS_ROW + seg * 4) * 4); \
            cp16(sA + off, Ag + (size_t)row * DD + _c * BK + seg * 4);         \
            cp16(sW + off, Wg + (size_t)row * DD + _c * BK + seg * 4);         \
        }                                                                      \
        asm volatile("cp.async.commit_group;" ::: "memory");                   \
    } while (0)

    ISSUE(0, 0);
    const int NCH = DD / BK;
    for (int c = 0; c < NCH; c++) {
        const int st = c & 1;
        if (c + 1 < NCH) {
            ISSUE(c + 1, st ^ 1);
            asm volatile("cp.async.wait_group 1;" ::: "memory");
        } else {
            asm volatile("cp.async.wait_group 0;" ::: "memory");
        }
        __syncthreads();

        const float* as = As + st * STAGE_FLOATS;
        const float* ws = Ws + st * STAGE_FLOATS;
#pragma unroll
        for (int kk = 0; kk < 4; kk++) {
            const int k0 = kk * 8;
            uint32_t af[2][4], bf[8][2];
#pragma unroll
            for (int mt = 0; mt < 2; mt++) {
                const float* base = as + (wm + mt * 16 + g) * LDS_ROW + k0;
                af[mt][0] = __float_as_uint(base[q]);
                af[mt][1] = __float_as_uint(base[8 * LDS_ROW + q]);
                af[mt][2] = __float_as_uint(base[q + 4]);
                af[mt][3] = __float_as_uint(base[8 * LDS_ROW + q + 4]);
            }
#pragma unroll
            for (int nt = 0; nt < 8; nt++) {
                const float* base = ws + (wn + nt * 8 + g) * LDS_ROW + k0;
                bf[nt][0] = __float_as_uint(base[q]);
                bf[nt][1] = __float_as_uint(base[q + 4]);
            }
#pragma unroll
            for (int mt = 0; mt < 2; mt++)
#pragma unroll
                for (int nt = 0; nt < 8; nt++)
                    mma_tf32(acc[mt][nt], af[mt], bf[nt]);
        }
        __syncthreads();
    }
#undef ISSUE

#pragma unroll
    for (int mt = 0; mt < 2; mt++) {
#pragma unroll
        for (int nt = 0; nt < 8; nt++) {
            const int r0 = m0 + wm + mt * 16 + g;
            const int cc = n0 + wn + nt * 8 + 2 * q;
            float v0x = acc[mt][nt][0], v0y = acc[mt][nt][1];
            float v1x = acc[mt][nt][2], v1y = acc[mt][nt][3];
            if (ROUND) {
                v0x = rna_tf32(v0x); v0y = rna_tf32(v0y);
                v1x = rna_tf32(v1x); v1y = rna_tf32(v1y);
            }
            *(float2*)(C + (size_t)r0 * DD + cc) = make_float2(v0x, v0y);
            *(float2*)(C + (size_t)(r0 + 8) * DD + cc) = make_float2(v1x, v1y);
        }
    }
}

__global__ void __launch_bounds__(256) gemm_qkv_kernel() {
    const float* B;
    float* C;
    if (blockIdx.z == 0) { B = g_wq; C = g_q; }
    else if (blockIdx.z == 1) { B = g_wk; C = g_k; }
    else { B = g_wv; C = g_v; }
    gemm_body<true>(g_x, B, C);   // round outputs -> attention reads tf32
}

__global__ void __launch_bounds__(256) gemm_out_kernel(float* __restrict__ out) {
    gemm_body<false>(g_attn, g_wo, out);  // final output: full fp32
}

// ---------------------------------------------------------------------------
// Round fp32 -> nearest tf32
// ---------------------------------------------------------------------------
__global__ void __launch_bounds__(256) round_tf32_kernel(const float* __restrict__ in,
                                                         float* __restrict__ out, int n4) {
    int i = blockIdx.x * blockDim.x + threadIdx.x;
    if (i < n4) {
        float4 v = ((const float4*)in)[i];
        v.x = rna_tf32(v.x); v.y = rna_tf32(v.y);
        v.z = rna_tf32(v.z); v.w = rna_tf32(v.w);
        ((float4*)out)[i] = v;
    }
}

// ---------------------------------------------------------------------------
// Tensor-core causal flash attention (tf32 mma.sync).
// CTA: 128 queries (8 warps x 16 rows) of one (b,h); key tiles of 64,
// double-buffered via cp.async. P round-trips through smem (per-warp rows).
// ---------------------------------------------------------------------------
#define ASR 68                                   // smem row stride (floats)
#define QS_OFF 0                                 // 128*68 = 8704 (aliased by Ps)
#define KV_OFF(st) (8704 + (st) * 8704)          // per stage: Ks 64*68, Vs 64*68
#define VS_REL 4352
#define ATT_SMEM_BYTES ((8704 + 2 * 8704) * 4)   // 104448 B

__global__ void __launch_bounds__(256, 2) attn_mma_kernel() {
    extern __shared__ float sm[];
    const uint32_t sb = smem_u32(sm);
    const int tid = threadIdx.x, w = tid >> 5, lane = tid & 31;
    const int g = lane >> 2, q = lane & 3;
    const int wm = w * 16;
    const int qt = blockIdx.x, bh = blockIdx.y;
    const int b = bh >> 4, h = bh & 15;
    const int row0 = qt * 128;

    const float* Qg = g_q + ((size_t)(b * SS + row0)) * DD + h * DKK;
    const float* Kg = g_k + ((size_t)(b * SS)) * DD + h * DKK;
    const float* Vg = g_v + ((size_t)(b * SS)) * DD + h * DKK;

    // Q tile -> Qs (group 0)
#pragma unroll
    for (int i = 0; i < 8; i++) {
        int f = i * 256 + tid;
        int row = f >> 4, seg = f & 15;
        cp16(sb + (uint32_t)((QS_OFF + row * ASR + seg * 4) * 4),
             Qg + (size_t)row * DD + seg * 4);
    }
    asm volatile("cp.async.commit_group;" ::: "memory");

#define ISSUE_KV(j, st) do {                                                   \
        int _j = (j), _s = (st);                                               \
        _Pragma("unroll")                                                      \
        for (int i = 0; i < 4; i++) {                                          \
            int f = i * 256 + tid;                                             \
            int r = f >> 4, sg = f & 15;                                       \
            uint32_t o = (uint32_t)((KV_OFF(_s) + r * ASR + sg * 4) * 4);      \
            cp16(sb + o, Kg + (size_t)(_j * 64 + r) * DD + sg * 4);            \
            cp16(sb + o + (uint32_t)(VS_REL * 4),                              \
                 Vg + (size_t)(_j * 64 + r) * DD + sg * 4);                    \
        }                                                                      \
        asm volatile("cp.async.commit_group;" ::: "memory");                   \
    } while (0)

    ISSUE_KV(0, 0);
    asm volatile("cp.async.wait_group 1;" ::: "memory");  // Q tile landed
    __syncthreads();

    // Q A-fragments (scale 1/8 folded; inputs already tf32, *2^-3 exact)
    uint32_t qa[8][4];
#pragma unroll
    for (int kk = 0; kk < 8; kk++) {
        const float* r0p = sm + QS_OFF + (wm + g) * ASR + kk * 8;
        const float* r1p = sm + QS_OFF + (wm + g + 8) * ASR + kk * 8;
        qa[kk][0] = __float_as_uint(r0p[q] * 0.125f);
        qa[kk][1] = __float_as_uint(r1p[q] * 0.125f);
        qa[kk][2] = __float_as_uint(r0p[q + 4] * 0.125f);
        qa[kk][3] = __float_as_uint(r1p[q + 4] * 0.125f);
    }

    float acc[8][4];
#pragma unroll
    for (int nt = 0; nt < 8; nt++)
#pragma unroll
        for (int i = 0; i < 4; i++) acc[nt][i] = 0.f;
    float m0r = -1e30f, m1r = -1e30f, l0r = 0.f, l1r = 0.f;

    const int jmax = 2 * qt + 2;
    for (int j = 0; j < jmax; j++) {
        const int st = j & 1;
        if (j + 1 < jmax) {
            ISSUE_KV(j + 1, st ^ 1);
            asm volatile("cp.async.wait_group 1;" ::: "memory");
        } else {
            asm volatile("cp.async.wait_group 0;" ::: "memory");
        }
        __syncthreads();

        // warp-level early-out on fully masked tiles (uniform per warp)
        const bool active = (j * 64 <= row0 + wm + 15);
        if (active) {
            // ---- S = Q K^T ----
            float sc[8][4];
#pragma unroll
            for (int nt = 0; nt < 8; nt++)
#pragma unroll
                for (int i = 0; i < 4; i++) sc[nt][i] = 0.f;
            const float* ks = sm + KV_OFF(st);
#pragma unroll
            for (int kk = 0; kk < 8; kk++) {
                uint32_t bf[8][2];
#pragma unroll
                for (int nt = 0; nt < 8; nt++) {
                    const float* base = ks + (nt * 8 + g) * ASR + kk * 8;
                    bf[nt][0] = __float_as_uint(base[q]);
                    bf[nt][1] = __float_as_uint(base[q + 4]);
                }
#pragma unroll
                for (int nt = 0; nt < 8; nt++)
                    mma_tf32(sc[nt], qa[kk], bf[nt]);
            }

            // causal mask (diagonal tiles only)
            if (j >= 2 * qt) {
                const int rg0 = row0 + wm + g, rg1 = rg0 + 8;
#pragma unroll
                for (int nt = 0; nt < 8; nt++) {
                    const int cg = j * 64 + nt * 8 + 2 * q;
                    if (cg > rg0)     sc[nt][0] = -1e30f;
                    if (cg + 1 > rg0) sc[nt][1] = -1e30f;
                    if (cg > rg1)     sc[nt][2] = -1e30f;
                    if (cg + 1 > rg1) sc[nt][3] = -1e30f;
                }
            }

            // ---- online softmax ----
            float mx0 = m0r, mx1 = m1r;
#pragma unroll
            for (int nt = 0; nt < 8; nt++) {
                mx0 = fmaxf(mx0, fmaxf(sc[nt][0], sc[nt][1]));
                mx1 = fmaxf(mx1, fmaxf(sc[nt][2], sc[nt][3]));
            }
            mx0 = fmaxf(mx0, __shfl_xor_sync(0xffffffffu, mx0, 1));
            mx0 = fmaxf(mx0, __shfl_xor_sync(0xffffffffu, mx0, 2));
            mx1 = fmaxf(mx1, __shfl_xor_sync(0xffffffffu, mx1, 1));
            mx1 = fmaxf(mx1, __shfl_xor_sync(0xffffffffu, mx1, 2));
            const float c0 = __expf(m0r - mx0), c1 = __expf(m1r - mx1);
            m0r = mx0; m1r = mx1;
            l0r *= c0; l1r *= c1;
#pragma unroll
            for (int nt = 0; nt < 8; nt++) {
                acc[nt][0] *= c0; acc[nt][1] *= c0;
                acc[nt][2] *= c1; acc[nt][3] *= c1;
            }
            float s0 = 0.f, s1 = 0.f;
            float* ps = sm + QS_OFF;
#pragma unroll
            for (int nt = 0; nt < 8; nt++) {
                float p00 = __expf(sc[nt][0] - mx0);
                float p01 = __expf(sc[nt][1] - mx0);
                float p10 = __expf(sc[nt][2] - mx1);
                float p11 = __expf(sc[nt][3] - mx1);
                s0 += p00 + p01; s1 += p10 + p11;
                *(float2*)(ps + (wm + g) * ASR + nt * 8 + 2 * q) =
                    make_float2(rna_tf32(p00), rna_tf32(p01));
                *(float2*)(ps + (wm + g + 8) * ASR + nt * 8 + 2 * q) =
                    make_float2(rna_tf32(p10), rna_tf32(p11));
            }
            s0 += __shfl_xor_sync(0xffffffffu, s0, 1);
            s0 += __shfl_xor_sync(0xffffffffu, s0, 2);
            s1 += __shfl_xor_sync(0xffffffffu, s1, 1);
            s1 += __shfl_xor_sync(0xffffffffu, s1, 2);
            l0r += s0; l1r += s1;
            __syncwarp();

            // ---- O += P V ----
            const float* vs = sm + KV_OFF(st) + VS_REL;
#pragma unroll
            for (int kk = 0; kk < 8; kk++) {
                uint32_t pa[4];
                const float* b0 = ps + (wm + g) * ASR + kk * 8;
                const float* b1 = ps + (wm + g + 8) * ASR + kk * 8;
                pa[0] = __float_as_uint(b0[q]);
                pa[1] = __float_as_uint(b1[q]);
                pa[2] = __float_as_uint(b0[q + 4]);
                pa[3] = __float_as_uint(b1[q + 4]);
#pragma unroll
                for (int nt = 0; nt < 8; nt++) {
                    uint32_t vb[2];
                    vb[0] = __float_as_uint(vs[(kk * 8 + q) * ASR + nt * 8 + g]);
                    vb[1] = __float_as_uint(vs[(kk * 8 + q + 4) * ASR + nt * 8 + g]);
                    mma_tf32(acc[nt], pa, vb);
                }
            }
        }
        __syncthreads();   // stage reads done before it is refilled
    }
#undef ISSUE_KV

    // epilogue: divide, round to tf32 (feeds out-GEMM), store
    const float inv0 = 1.f / l0r, inv1 = 1.f / l1r;
    float* O0 = g_attn + (size_t)(b * SS + row0 + wm + g) * DD + h * DKK;
    float* O1 = g_attn + (size_t)(b * SS + row0 + wm + g + 8) * DD + h * DKK;
#pragma unroll
    for (int nt = 0; nt < 8; nt++) {
        *(float2*)(O0 + nt * 8 + 2 * q) =
            make_float2(rna_tf32(acc[nt][0] * inv0), rna_tf32(acc[nt][1] * inv0));
        *(float2*)(O1 + nt * 8 + 2 * q) =
            make_float2(rna_tf32(acc[nt][2] * inv1), rna_tf32(acc[nt][3] * inv1));
    }
}

// ---------------------------------------------------------------------------
extern "C" void kernel_launch(void* const* d_in, const int* in_sizes, int n_in,
                              void* d_out, int out_size) {
    const float* x  = (const float*)d_in[0];
    const float* wq = (const float*)d_in[1];
    const float* wk = (const float*)d_in[2];
    const float* wv = (const float*)d_in[3];
    const float* wo = (const float*)d_in[4];
    float* out = (float*)d_out;

    cudaFuncSetAttribute(gemm_qkv_kernel, cudaFuncAttributeMaxDynamicSharedMemorySize, SMEM_BYTES_G);
    cudaFuncSetAttribute(gemm_out_kernel, cudaFuncAttributeMaxDynamicSharedMemorySize, SMEM_BYTES_G);
    cudaFuncSetAttribute(attn_mma_kernel, cudaFuncAttributeMaxDynamicSharedMemorySize, ATT_SMEM_BYTES);

    float *px, *pwq, *pwk, *pwv, *pwo;
    cudaGetSymbolAddress((void**)&px,  g_x);
    cudaGetSymbolAddress((void**)&pwq, g_wq);
    cudaGetSymbolAddress((void**)&pwk, g_wk);
    cudaGetSymbolAddress((void**)&pwv, g_wv);
    cudaGetSymbolAddress((void**)&pwo, g_wo);

    // Round GEMM inputs to nearest-tf32
    const int nx4 = MM * DD / 4, nw4 = DD * DD / 4;
    round_tf32_kernel<<<(nx4 + 255) / 256, 256>>>(x, px, nx4);
    round_tf32_kernel<<<(nw4 + 255) / 256, 256>>>(wq, pwq, nw4);
    round_tf32_kernel<<<(nw4 + 255) / 256, 256>>>(wk, pwk, nw4);
    round_tf32_kernel<<<(nw4 + 255) / 256, 256>>>(wv, pwv, nw4);
    round_tf32_kernel<<<(nw4 + 255) / 256, 256>>>(wo, pwo, nw4);

    // Q/K/V projections (tensor cores, tf32; outputs rounded to tf32)
    dim3 gproj(DD / 128, MM / 128, 3);
    gemm_qkv_kernel<<<gproj, 256, SMEM_BYTES_G>>>();

    // Causal flash attention on tensor cores
    dim3 gattn(SS / 128, BB * HH);
    attn_mma_kernel<<<gattn, 256, ATT_SMEM_BYTES>>>();

    // Output projection (tensor cores, tf32; full fp32 output)
    dim3 gout(DD / 128, MM / 128, 1);
    gemm_out_kernel<<<gout, 256, SMEM_BYTES_G>>>(out);
}